// round 3
// baseline (speedup 1.0000x reference)
#include <cuda_runtime.h>
#include <cuda_bf16.h>
#include <cstdint>

// PolyConv: h = sum_k theta[k] * L_sym^k x, L_sym = I - D^{-1/2} A D^{-1/2}
// N=100000 nodes, E=1600000 edges, F=64 features, k=0..4.

#define NN 100000
#define EE 1600000
#define FF 64

#define SCAN_BS 512
#define SCAN_NB ((NN + SCAN_BS - 1) / SCAN_BS)   // 196

// ---- persistent device scratch (allocation-free rule) ----
__device__ int   g_idx64;                // 1 if edge_index is int64, 0 if int32
__device__ int   g_cnt[NN];
__device__ int   g_local[NN];
__device__ int   g_bsum[SCAN_BS];        // >= SCAN_NB
__device__ int   g_rowptr[NN + 1];
__device__ int   g_cursor[NN];
__device__ int   g_csr[EE];
__device__ float g_dinv[NN];
__device__ float g_feat[2][NN * FF];     // ping-pong feature buffers

// Load edge index element i (0..2E-1) regardless of storage width.
__device__ __forceinline__ int load_idx(const void* __restrict__ ei, int i) {
    if (g_idx64) return (int)((const long long*)ei)[i];
    return ((const int*)ei)[i];
}

// ---------------------------------------------------------------------------
// 0) detect index width: if data is int64 (values < 2^31, nonneg), the hi
//    int32 word of every element is 0. For int32 data, 64 consecutive zero
//    edge values is impossible (p ~ 1e-320).
__global__ void k_detect(const int* __restrict__ ei32) {
    if (threadIdx.x == 0 && blockIdx.x == 0) {
        int is64 = 1;
        for (int i = 0; i < 64; i++) {
            if (ei32[2 * i + 1] != 0) { is64 = 0; break; }
        }
        g_idx64 = is64;
    }
}

// 1) zero counts
__global__ void k_zero_cnt() {
    int i = blockIdx.x * blockDim.x + threadIdx.x;
    if (i < NN) g_cnt[i] = 0;
}

// 2) in-degree histogram over dst
__global__ void k_hist(const void* __restrict__ ei) {
    int e = blockIdx.x * blockDim.x + threadIdx.x;
    if (e < EE) {
        int dst = load_idx(ei, EE + e);
        atomicAdd(&g_cnt[dst], 1);
    }
}

// 3) per-block exclusive scan of counts
__global__ void k_scan1() {
    __shared__ int sh[SCAN_BS];
    int tid = threadIdx.x;
    int gid = blockIdx.x * SCAN_BS + tid;
    int val = (gid < NN) ? g_cnt[gid] : 0;
    sh[tid] = val;
    __syncthreads();
    for (int off = 1; off < SCAN_BS; off <<= 1) {
        int t = (tid >= off) ? sh[tid - off] : 0;
        __syncthreads();
        sh[tid] += t;
        __syncthreads();
    }
    if (gid < NN) g_local[gid] = sh[tid] - val;   // exclusive-within-block
    if (tid == SCAN_BS - 1) g_bsum[blockIdx.x] = sh[tid];
}

// 4) scan of block sums (single block)
__global__ void k_scan2() {
    __shared__ int sh[SCAN_BS];
    int tid = threadIdx.x;
    int val = (tid < SCAN_NB) ? g_bsum[tid] : 0;
    sh[tid] = val;
    __syncthreads();
    for (int off = 1; off < SCAN_BS; off <<= 1) {
        int t = (tid >= off) ? sh[tid - off] : 0;
        __syncthreads();
        sh[tid] += t;
        __syncthreads();
    }
    if (tid < SCAN_NB) g_bsum[tid] = sh[tid] - val;  // exclusive
}

// 5) finalize rowptr, cursors, and dinv = rsqrt(max(deg,1))
__global__ void k_scan3() {
    int i = blockIdx.x * blockDim.x + threadIdx.x;
    if (i < NN) {
        int rp = g_local[i] + g_bsum[i / SCAN_BS];
        g_rowptr[i] = rp;
        g_cursor[i] = rp;
        int d = g_cnt[i];
        g_dinv[i] = rsqrtf((float)(d < 1 ? 1 : d));
    }
    if (i == 0) g_rowptr[NN] = EE;
}

// 6) fill CSR: group src indices by dst
__global__ void k_fill(const void* __restrict__ ei) {
    int e = blockIdx.x * blockDim.x + threadIdx.x;
    if (e < EE) {
        int src = load_idx(ei, e);
        int dst = load_idx(ei, EE + e);
        int p = atomicAdd(&g_cursor[dst], 1);
        g_csr[p] = src;
    }
}

// 7) fused SpMV + epilogue. One warp per row; lane covers features {lane, lane+32}.
//    feat_new = feat - dinv[r] * sum_{s in row} feat[s]*dinv[s]
//    first=1:  out = theta0*feat + theta*feat_new
//    first=0:  out += theta*feat_new
__global__ void k_spmv(const float* __restrict__ fin,
                       float* __restrict__ fout,
                       float* __restrict__ out,
                       float theta0, float theta, int first) {
    int gtid = blockIdx.x * blockDim.x + threadIdx.x;
    int row  = gtid >> 5;
    int lane = gtid & 31;
    if (row >= NN) return;

    int beg = g_rowptr[row];
    int end = g_rowptr[row + 1];

    float acc0 = 0.f, acc1 = 0.f;
    for (int e = beg; e < end; e++) {
        int   s  = g_csr[e];          // warp-broadcast load
        float ds = g_dinv[s];         // warp-broadcast load
        const float* fr = fin + (size_t)s * FF;
        acc0 = fmaf(fr[lane],      ds, acc0);
        acc1 = fmaf(fr[lane + 32], ds, acc1);
    }

    float dr = g_dinv[row];
    const float* fme = fin + (size_t)row * FF;
    float f0 = fme[lane], f1 = fme[lane + 32];
    float n0 = f0 - dr * acc0;
    float n1 = f1 - dr * acc1;

    float* fo = fout + (size_t)row * FF;
    fo[lane]      = n0;
    fo[lane + 32] = n1;

    float* o = out + (size_t)row * FF;
    if (first) {
        o[lane]      = theta0 * f0 + theta * n0;
        o[lane + 32] = theta0 * f1 + theta * n1;
    } else {
        o[lane]      += theta * n0;
        o[lane + 32] += theta * n1;
    }
}

extern "C" void kernel_launch(void* const* d_in, const int* in_sizes, int n_in,
                              void* d_out, int out_size) {
    const float* x   = (const float*)d_in[0];
    const void*  ei  = d_in[1];
    float*       out = (float*)d_out;

    // resolve device-global scratch pointers
    float* feat0; float* feat1;
    cudaGetSymbolAddress((void**)&feat0, g_feat);
    feat1 = feat0 + (size_t)NN * FF;

    const int TB = 256;
    // CSR build
    k_detect<<<1, 32>>>((const int*)ei);
    k_zero_cnt<<<(NN + TB - 1) / TB, TB>>>();
    k_hist<<<(EE + TB - 1) / TB, TB>>>(ei);
    k_scan1<<<SCAN_NB, SCAN_BS>>>();
    k_scan2<<<1, SCAN_BS>>>();
    k_scan3<<<(NN + TB - 1) / TB, TB>>>();
    k_fill<<<(EE + TB - 1) / TB, TB>>>(ei);

    // 4 fused SpMV iterations (theta = 0.6, -0.4, 0.3, -0.2, 0.1)
    const long long threads = (long long)NN * 32;
    const int blocks = (int)((threads + TB - 1) / TB);
    k_spmv<<<blocks, TB>>>(x,     feat0, out, 0.6f, -0.4f, 1);
    k_spmv<<<blocks, TB>>>(feat0, feat1, out, 0.0f,  0.3f, 0);
    k_spmv<<<blocks, TB>>>(feat1, feat0, out, 0.0f, -0.2f, 0);
    k_spmv<<<blocks, TB>>>(feat0, feat1, out, 0.0f,  0.1f, 0);
}

// round 4
// speedup vs baseline: 1.0821x; 1.0821x over previous
#include <cuda_runtime.h>
#include <cuda_bf16.h>
#include <cstdint>

// PolyConv: h = sum_k theta[k] * L_sym^k x, L_sym = I - D^{-1/2} A D^{-1/2}
// N=100000 nodes, E=1600000 edges, F=64 features, k=0..4.

#define NN 100000
#define EE 1600000
#define FF 64

// ---- persistent device scratch (allocation-free rule) ----
__device__ int   g_idx64;                // 1 if edge_index is int64, 0 if int32
__device__ int   g_total;                // CSR allocation cursor
__device__ int   g_cnt[NN];              // in-degree
__device__ int   g_beg[NN];              // row segment start (non-contiguous alloc)
__device__ int   g_cursor[NN];           // fill cursor
__device__ int   g_csr[EE];              // src indices grouped by dst
__device__ float g_dinv[NN];             // rsqrt(max(deg,1))
__device__ float g_feat[2][NN * FF];     // ping-pong feature buffers

// Load edge index element i (0..2E-1) regardless of storage width.
__device__ __forceinline__ int load_idx(const void* __restrict__ ei, int i) {
    if (g_idx64) return (int)((const long long*)ei)[i];
    return ((const int*)ei)[i];
}

// ---------------------------------------------------------------------------
// 0) detect index width: int64 values < 2^31 have zero hi-words; 64 straight
//    zero edge-values in int32 data is impossible for random indices in [0,1e5).
__global__ void k_detect(const int* __restrict__ ei32) {
    if (threadIdx.x == 0) {
        int is64 = 1;
        for (int i = 0; i < 64; i++)
            if (ei32[2 * i + 1] != 0) { is64 = 0; break; }
        g_idx64 = is64;
    }
}

// 1) zero counts + total
__global__ void k_zero() {
    int i = blockIdx.x * blockDim.x + threadIdx.x;
    if (i < NN) g_cnt[i] = 0;
    if (i == 0) g_total = 0;
}

// 2) in-degree histogram over dst (4 edges/thread, coalesced wide loads)
__global__ void k_hist(const void* __restrict__ ei) {
    int base = (blockIdx.x * blockDim.x + threadIdx.x) * 4;
    #pragma unroll
    for (int j = 0; j < 4; j++) {
        int e = base + j;
        if (e < EE) atomicAdd(&g_cnt[load_idx(ei, EE + e)], 1);
    }
}

// 3) scan-free segment allocation + dinv. Segments are assigned in arbitrary
//    order but each row owns exactly [beg, beg+cnt), which is all spmv needs.
__global__ void k_alloc() {
    int i = blockIdx.x * blockDim.x + threadIdx.x;
    if (i < NN) {
        int c = g_cnt[i];
        int rp = atomicAdd(&g_total, c);
        g_beg[i] = rp;
        g_cursor[i] = rp;
        g_dinv[i] = rsqrtf((float)(c < 1 ? 1 : c));
    }
}

// 4) fill CSR: group src indices by dst
__global__ void k_fill(const void* __restrict__ ei) {
    int base = (blockIdx.x * blockDim.x + threadIdx.x) * 4;
    #pragma unroll
    for (int j = 0; j < 4; j++) {
        int e = base + j;
        if (e < EE) {
            int src = load_idx(ei, e);
            int dst = load_idx(ei, EE + e);
            int p = atomicAdd(&g_cursor[dst], 1);
            g_csr[p] = src;
        }
    }
}

// 5) fused SpMV + epilogue. One warp per row; lane owns features {2*lane, 2*lane+1}.
//    feat_new = feat - dinv[r] * sum_{s in row} feat[s]*dinv[s]
//    FIRST=1:  out = theta0*feat + theta*feat_new
//    FIRST=0:  out += theta*feat_new
template <int FIRST, int WRITE_FOUT>
__global__ void __launch_bounds__(256) k_spmv(const float* __restrict__ fin,
                                              float* __restrict__ fout,
                                              float* __restrict__ out,
                                              float theta0, float theta) {
    int gtid = blockIdx.x * blockDim.x + threadIdx.x;
    int row  = gtid >> 5;
    int lane = gtid & 31;
    if (row >= NN) return;

    int beg = g_beg[row];
    int end = beg + g_cnt[row];

    const float2* __restrict__ f2 = (const float2*)fin;
    float2 acc = make_float2(0.f, 0.f);

    int e = beg;
    for (; e + 2 <= end; e += 2) {
        int s0 = g_csr[e];
        int s1 = g_csr[e + 1];
        float d0 = g_dinv[s0];
        float d1 = g_dinv[s1];
        float2 a = __ldg(&f2[s0 * 32 + lane]);
        float2 b = __ldg(&f2[s1 * 32 + lane]);
        acc.x = fmaf(b.x, d1, fmaf(a.x, d0, acc.x));
        acc.y = fmaf(b.y, d1, fmaf(a.y, d0, acc.y));
    }
    if (e < end) {
        int s0 = g_csr[e];
        float d0 = g_dinv[s0];
        float2 a = __ldg(&f2[s0 * 32 + lane]);
        acc.x = fmaf(a.x, d0, acc.x);
        acc.y = fmaf(a.y, d0, acc.y);
    }

    float dr = g_dinv[row];
    float2 f = __ldg(&f2[row * 32 + lane]);
    float2 n = make_float2(f.x - dr * acc.x, f.y - dr * acc.y);

    if (WRITE_FOUT) {
        ((float2*)fout)[row * 32 + lane] = n;
    }

    float2* o = (float2*)out + row * 32 + lane;
    if (FIRST) {
        *o = make_float2(theta0 * f.x + theta * n.x,
                         theta0 * f.y + theta * n.y);
    } else {
        float2 v = *o;
        *o = make_float2(fmaf(theta, n.x, v.x), fmaf(theta, n.y, v.y));
    }
}

extern "C" void kernel_launch(void* const* d_in, const int* in_sizes, int n_in,
                              void* d_out, int out_size) {
    const float* x   = (const float*)d_in[0];
    const void*  ei  = d_in[1];
    float*       out = (float*)d_out;

    float* feat0; float* feat1;
    cudaGetSymbolAddress((void**)&feat0, g_feat);
    feat1 = feat0 + (size_t)NN * FF;

    const int TB = 256;
    // CSR build
    k_detect<<<1, 32>>>((const int*)ei);
    k_zero<<<(NN + TB - 1) / TB, TB>>>();
    k_hist<<<(EE / 4 + TB - 1) / TB, TB>>>(ei);
    k_alloc<<<(NN + TB - 1) / TB, TB>>>();
    k_fill<<<(EE / 4 + TB - 1) / TB, TB>>>(ei);

    // 4 fused SpMV iterations (theta = 0.6, -0.4, 0.3, -0.2, 0.1)
    const long long threads = (long long)NN * 32;
    const int blocks = (int)((threads + TB - 1) / TB);
    k_spmv<1, 1><<<blocks, TB>>>(x,     feat0, out, 0.6f, -0.4f);
    k_spmv<0, 1><<<blocks, TB>>>(feat0, feat1, out, 0.0f,  0.3f);
    k_spmv<0, 1><<<blocks, TB>>>(feat1, feat0, out, 0.0f, -0.2f);
    k_spmv<0, 0><<<blocks, TB>>>(feat0, feat1, out, 0.0f,  0.1f);
}